// round 1
// baseline (speedup 1.0000x reference)
#include <cuda_runtime.h>

typedef unsigned long long ull;

#define H_RES 150

// Transposed planes: per scale s (W = 64<<s), layout [3, H, W, 16] (channels contiguous).
// Sizes: 460800, 921600, 1843200, 3686400 floats; offsets 0, 460800, 1382400, 3225600.
__device__ __align__(16) float g_planes[6912000];
__device__ __align__(16) float g_w0t[64 * 128];   // w0t[k*128 + j] = w0[j*64 + k]
__device__ __align__(16) float g_w2t[128 * 64];   // w2t[j*64 + o]  = w2[o*128 + j]

// ---- packed f32x2 helpers (sm_100+ PTX; ptxas never emits FFMA2 from C++) ----
__device__ __forceinline__ ull fma2(ull a, ull b, ull c) {
    ull d;
    asm("fma.rn.f32x2 %0, %1, %2, %3;" : "=l"(d) : "l"(a), "l"(b), "l"(c));
    return d;
}
__device__ __forceinline__ ull pack2(float lo, float hi) {
    ull r;
    asm("mov.b64 %0, {%1, %2};" : "=l"(r) : "f"(lo), "f"(hi));
    return r;
}
__device__ __forceinline__ float2 unpack2(ull a) {
    float2 f;
    asm("mov.b64 {%0, %1}, %2;" : "=f"(f.x), "=f"(f.y) : "l"(a));
    return f;
}
__device__ __forceinline__ ull relu2(ull a) {
    float2 f = unpack2(a);
    return pack2(fmaxf(f.x, 0.0f), fmaxf(f.y, 0.0f));
}

// ---- prologue: transpose planes [3,16,150,W] -> [3,150,W,16] ----
__global__ void transpose_plane_kernel(const float* __restrict__ src, int dstoff, int W) {
    int total = 7200 * W;  // 3*16*150*W
    for (int i = blockIdx.x * blockDim.x + threadIdx.x; i < total;
         i += gridDim.x * blockDim.x) {
        int c = i & 15;
        int rest = i >> 4;
        int x = rest % W; rest /= W;
        int y = rest % H_RES;
        int p = rest / H_RES;
        g_planes[dstoff + i] = src[((p * 16 + c) * H_RES + y) * W + x];
    }
}

// ---- prologue: transpose w0 [128,64] and w2 [64,128] ----
__global__ void transpose_w_kernel(const float* __restrict__ w0,
                                   const float* __restrict__ w2) {
    int i = blockIdx.x * blockDim.x + threadIdx.x;
    if (i < 64 * 128) {
        int k = i >> 7, j = i & 127;         // g_w0t[k*128+j]
        g_w0t[i] = w0[j * 64 + k];
        int jj = i >> 6, o = i & 63;         // g_w2t[jj*64+o]
        g_w2t[i] = w2[o * 128 + jj];
    }
}

// ---- fused: sample 4 scales x 3 planes (bilinear, product) -> MLP 64->128->128->64 ----
__global__ void __launch_bounds__(128, 2) fused_kernel(
    const float4* __restrict__ pts,
    const float*  __restrict__ b0,
    const float*  __restrict__ w1,
    const float*  __restrict__ b1,
    const float*  __restrict__ b2,
    float*        __restrict__ out,
    int n)
{
    __shared__ float feats_s[64 * 128];   // [k][tid], conflict-free
    const int tid = threadIdx.x;
    const int pt  = blockIdx.x * 128 + tid;
    if (pt >= n) return;

    float4 P = pts[pt];

    // time coordinate -> height (H = 150), shared by all 12 planes
    float fy = (P.w + 1.0f) * 0.5f * (float)(H_RES - 1);
    fy = fminf(fmaxf(fy, 0.0f), (float)(H_RES - 1));
    int   iy0 = (int)floorf(fy);
    int   iy1 = min(iy0 + 1, H_RES - 1);
    float wyv = fy - (float)iy0;

    float coord[3] = {P.x, P.y, P.z};
    const int scale_off[4] = {0, 460800, 1382400, 3225600};

#pragma unroll
    for (int s = 0; s < 4; s++) {
        const int W = 64 << s;
        float prod[16];
#pragma unroll
        for (int c = 0; c < 16; c++) prod[c] = 1.0f;

#pragma unroll
        for (int p = 0; p < 3; p++) {
            float x  = coord[p];
            float fx = (x + 1.0f) * 0.5f * (float)(W - 1);
            fx = fminf(fmaxf(fx, 0.0f), (float)(W - 1));
            int   ix0 = (int)floorf(fx);
            int   ix1 = min(ix0 + 1, W - 1);
            float wx  = fx - (float)ix0;

            const float* pb = g_planes + scale_off[s] + p * (H_RES * W * 16);
            const float4* r00 = (const float4*)(pb + (iy0 * W + ix0) * 16);
            const float4* r01 = (const float4*)(pb + (iy0 * W + ix1) * 16);
            const float4* r10 = (const float4*)(pb + (iy1 * W + ix0) * 16);
            const float4* r11 = (const float4*)(pb + (iy1 * W + ix1) * 16);

            float w00 = (1.0f - wx) * (1.0f - wyv);
            float w01 = wx * (1.0f - wyv);
            float w10 = (1.0f - wx) * wyv;
            float w11 = wx * wyv;

#pragma unroll
            for (int q = 0; q < 4; q++) {
                float4 a = r00[q], b = r01[q], c4 = r10[q], d = r11[q];
                prod[4*q+0] *= a.x*w00 + b.x*w01 + c4.x*w10 + d.x*w11;
                prod[4*q+1] *= a.y*w00 + b.y*w01 + c4.y*w10 + d.y*w11;
                prod[4*q+2] *= a.z*w00 + b.z*w01 + c4.z*w10 + d.z*w11;
                prod[4*q+3] *= a.w*w00 + b.w*w01 + c4.w*w10 + d.w*w11;
            }
        }
#pragma unroll
        for (int c = 0; c < 16; c++) feats_s[(s * 16 + c) * 128 + tid] = prod[c];
    }

    // ---- layer 0: h[128] = relu(w0 @ f + b0), packed f32x2 accumulators ----
    ull h2[64];
    {
        const ull* b0p = (const ull*)b0;
#pragma unroll
        for (int j2 = 0; j2 < 64; j2++) h2[j2] = b0p[j2];
    }
#pragma unroll 1
    for (int k = 0; k < 64; k++) {
        float fk  = feats_s[k * 128 + tid];
        ull   fk2 = pack2(fk, fk);
        const ulonglong2* wr = (const ulonglong2*)(g_w0t + k * 128);
#pragma unroll
        for (int j4 = 0; j4 < 32; j4++) {
            ulonglong2 wv = wr[j4];
            h2[2*j4]     = fma2(wv.x, fk2, h2[2*j4]);
            h2[2*j4 + 1] = fma2(wv.y, fk2, h2[2*j4 + 1]);
        }
    }
#pragma unroll
    for (int j2 = 0; j2 < 64; j2++) h2[j2] = relu2(h2[j2]);

    // ---- layer 1 + layer 2 fused: stream over j, never materialize h2 ----
    ull acc2[32];
    {
        const ull* b2p = (const ull*)b2;
#pragma unroll
        for (int o2 = 0; o2 < 32; o2++) acc2[o2] = b2p[o2];
    }
#pragma unroll 1
    for (int j = 0; j < 128; j++) {
        ull sa = 0ull, sb = 0ull;  // bits 0 == packed (+0.f,+0.f)
        const ulonglong2* wr = (const ulonglong2*)(w1 + j * 128);
#pragma unroll
        for (int k4 = 0; k4 < 32; k4++) {
            ulonglong2 wv = wr[k4];
            sa = fma2(wv.x, h2[2*k4],     sa);
            sb = fma2(wv.y, h2[2*k4 + 1], sb);
        }
        float2 fa = unpack2(sa), fb = unpack2(sb);
        float hj = b1[j] + ((fa.x + fa.y) + (fb.x + fb.y));
        hj = fmaxf(hj, 0.0f);
        ull hj2 = pack2(hj, hj);
        const ulonglong2* w2r = (const ulonglong2*)(g_w2t + j * 64);
#pragma unroll
        for (int o4 = 0; o4 < 16; o4++) {
            ulonglong2 wv = w2r[o4];
            acc2[2*o4]     = fma2(wv.x, hj2, acc2[2*o4]);
            acc2[2*o4 + 1] = fma2(wv.y, hj2, acc2[2*o4 + 1]);
        }
    }

    ulonglong2* op = (ulonglong2*)(out + (size_t)pt * 64);
#pragma unroll
    for (int o4 = 0; o4 < 16; o4++) {
        ulonglong2 v;
        v.x = acc2[2*o4];
        v.y = acc2[2*o4 + 1];
        op[o4] = v;
    }
}

extern "C" void kernel_launch(void* const* d_in, const int* in_sizes, int n_in,
                              void* d_out, int out_size) {
    const float* pts = (const float*)d_in[0];
    const float* p0  = (const float*)d_in[1];
    const float* p1  = (const float*)d_in[2];
    const float* p2  = (const float*)d_in[3];
    const float* p3  = (const float*)d_in[4];
    const float* w0  = (const float*)d_in[5];
    const float* b0  = (const float*)d_in[6];
    const float* w1  = (const float*)d_in[7];
    const float* b1  = (const float*)d_in[8];
    const float* w2  = (const float*)d_in[9];
    const float* b2  = (const float*)d_in[10];

    int n = in_sizes[0] / 4;

    transpose_plane_kernel<<<1024, 256>>>(p0, 0,       64);
    transpose_plane_kernel<<<2048, 256>>>(p1, 460800,  128);
    transpose_plane_kernel<<<2048, 256>>>(p2, 1382400, 256);
    transpose_plane_kernel<<<4096, 256>>>(p3, 3225600, 512);
    transpose_w_kernel<<<32, 256>>>(w0, w2);

    fused_kernel<<<(n + 127) / 128, 128>>>((const float4*)pts, b0, w1, b1, b2,
                                           (float*)d_out, n);
}

// round 2
// speedup vs baseline: 1.9565x; 1.9565x over previous
#include <cuda_runtime.h>

typedef unsigned long long ull;

#define H_RES 150

// Transposed planes: per scale s (W = 64<<s), layout [3, H, W, 16] (channels contiguous).
// Offsets (floats): 0, 460800, 1382400, 3225600; total 6912000.
__device__ __align__(16) float g_planes[6912000];

// ---- packed f32x2 helpers ----
__device__ __forceinline__ ull fma2(ull a, ull b, ull c) {
    ull d;
    asm("fma.rn.f32x2 %0, %1, %2, %3;" : "=l"(d) : "l"(a), "l"(b), "l"(c));
    return d;
}
__device__ __forceinline__ ull pack2(float lo, float hi) {
    ull r;
    asm("mov.b64 %0, {%1, %2};" : "=l"(r) : "f"(lo), "f"(hi));
    return r;
}
__device__ __forceinline__ float2 unpack2(ull a) {
    float2 f;
    asm("mov.b64 {%0, %1}, %2;" : "=f"(f.x), "=f"(f.y) : "l"(a));
    return f;
}
__device__ __forceinline__ ull relu2(ull a) {
    float2 f = unpack2(a);
    return pack2(fmaxf(f.x, 0.0f), fmaxf(f.y, 0.0f));
}

// ---- prologue (single launch): transpose all 4 plane sets [3,16,150,W]->[3,150,W,16] ----
__global__ void prep_kernel(const float* __restrict__ p0, const float* __restrict__ p1,
                            const float* __restrict__ p2, const float* __restrict__ p3) {
    const int total = 6912000;
    for (int i = blockIdx.x * blockDim.x + threadIdx.x; i < total;
         i += gridDim.x * blockDim.x) {
        int s, base;
        const float* src;
        if (i < 460800)       { s = 0; base = 0;       src = p0; }
        else if (i < 1382400) { s = 1; base = 460800;  src = p1; }
        else if (i < 3225600) { s = 2; base = 1382400; src = p2; }
        else                  { s = 3; base = 3225600; src = p3; }
        int W = 64 << s;
        int li = i - base;
        int c = li & 15;
        int rest = li >> 4;
        int x = rest % W; rest /= W;
        int y = rest % H_RES;
        int p = rest / H_RES;
        g_planes[i] = src[((p * 16 + c) * H_RES + y) * W + x];
    }
}

// smem layout (floats):
//  sW0t  [0,8192)        w0t[k*128+j]
//  sW1   [8192,24576)    w1[j*128+k]
//  sW2t  [24576,32768)   w2t[j*64+o]
//  sB0   [32768,32896)
//  sB1   [32896,33024)
//  sB2   [33024,33088)
//  feats [33088,49472)   [k][tid] stride 256
#define OFF_W1   8192
#define OFF_W2T  24576
#define OFF_B0   32768
#define OFF_B1   32896
#define OFF_B2   33024
#define OFF_FEAT 33088
#define SMEM_FLOATS 49472

// ---- persistent fused kernel: sample 12 planes -> product feats -> MLP 64->128->128->64 ----
__global__ void __launch_bounds__(256, 1) fused_kernel(
    const float4* __restrict__ pts,
    const float*  __restrict__ w0,
    const float*  __restrict__ b0,
    const float*  __restrict__ w1,
    const float*  __restrict__ b1,
    const float*  __restrict__ w2,
    const float*  __restrict__ b2,
    float*        __restrict__ out,
    int n, int ntiles)
{
    extern __shared__ float sm[];
    const int tid = threadIdx.x;

    // ---- one-time per block: stage weights (transposing w0, w2) + biases into smem ----
    for (int i = tid; i < 8192; i += 256) {
        int k = i >> 7, j = i & 127;
        sm[i] = w0[j * 64 + k];
    }
    for (int i = tid; i < 4096; i += 256)
        ((float4*)(sm + OFF_W1))[i] = ((const float4*)w1)[i];
    for (int i = tid; i < 8192; i += 256) {
        int j = i >> 6, o = i & 63;
        sm[OFF_W2T + i] = w2[o * 128 + j];
    }
    if (tid < 128) {
        sm[OFF_B0 + tid] = b0[tid];
        sm[OFF_B1 + tid] = b1[tid];
        if (tid < 64) sm[OFF_B2 + tid] = b2[tid];
    }
    __syncthreads();

    float* feats_s = sm + OFF_FEAT;
    const int scale_off[4] = {0, 460800, 1382400, 3225600};

    for (int t = blockIdx.x; t < ntiles; t += gridDim.x) {
        int pt = t * 256 + tid;
        if (pt >= n) continue;

        float4 P = pts[pt];

        // time -> height (H = 150), shared by all 12 planes
        float fy = (P.w + 1.0f) * 0.5f * (float)(H_RES - 1);
        fy = fminf(fmaxf(fy, 0.0f), (float)(H_RES - 1));
        int   iy0 = (int)floorf(fy);
        int   iy1 = min(iy0 + 1, H_RES - 1);
        float wyv = fy - (float)iy0;

        float coord[3] = {P.x, P.y, P.z};

#pragma unroll
        for (int s = 0; s < 4; s++) {
            const int W = 64 << s;
            float prod[16];
#pragma unroll
            for (int c = 0; c < 16; c++) prod[c] = 1.0f;

#pragma unroll
            for (int p = 0; p < 3; p++) {
                float x  = coord[p];
                float fx = (x + 1.0f) * 0.5f * (float)(W - 1);
                fx = fminf(fmaxf(fx, 0.0f), (float)(W - 1));
                int   ix0 = (int)floorf(fx);
                int   ix1 = min(ix0 + 1, W - 1);
                float wx  = fx - (float)ix0;

                const float* pb = g_planes + scale_off[s] + p * (H_RES * W * 16);
                const float4* r00 = (const float4*)(pb + (iy0 * W + ix0) * 16);
                const float4* r01 = (const float4*)(pb + (iy0 * W + ix1) * 16);
                const float4* r10 = (const float4*)(pb + (iy1 * W + ix0) * 16);
                const float4* r11 = (const float4*)(pb + (iy1 * W + ix1) * 16);

                float w00 = (1.0f - wx) * (1.0f - wyv);
                float w01 = wx * (1.0f - wyv);
                float w10 = (1.0f - wx) * wyv;
                float w11 = wx * wyv;

#pragma unroll
                for (int q = 0; q < 4; q++) {
                    float4 a = r00[q], b = r01[q], c4 = r10[q], d = r11[q];
                    prod[4*q+0] *= a.x*w00 + b.x*w01 + c4.x*w10 + d.x*w11;
                    prod[4*q+1] *= a.y*w00 + b.y*w01 + c4.y*w10 + d.y*w11;
                    prod[4*q+2] *= a.z*w00 + b.z*w01 + c4.z*w10 + d.z*w11;
                    prod[4*q+3] *= a.w*w00 + b.w*w01 + c4.w*w10 + d.w*w11;
                }
            }
#pragma unroll
            for (int c = 0; c < 16; c++) feats_s[(s * 16 + c) * 256 + tid] = prod[c];
        }

        // ---- layer 0: h[128] = relu(w0 @ f + b0) ----
        ull h2[64];
        {
            const ull* b0p = (const ull*)(sm + OFF_B0);
#pragma unroll
            for (int j2 = 0; j2 < 64; j2++) h2[j2] = b0p[j2];
        }
#pragma unroll 1
        for (int k = 0; k < 64; k++) {
            float fk  = feats_s[k * 256 + tid];
            ull   fk2 = pack2(fk, fk);
            const ulonglong2* wr = (const ulonglong2*)(sm + k * 128);
#pragma unroll
            for (int j4 = 0; j4 < 32; j4++) {
                ulonglong2 wv = wr[j4];
                h2[2*j4]     = fma2(wv.x, fk2, h2[2*j4]);
                h2[2*j4 + 1] = fma2(wv.y, fk2, h2[2*j4 + 1]);
            }
        }
#pragma unroll
        for (int j2 = 0; j2 < 64; j2++) h2[j2] = relu2(h2[j2]);

        // ---- layer 1 + layer 2 fused: stream over j ----
        ull acc2[32];
        {
            const ull* b2p = (const ull*)(sm + OFF_B2);
#pragma unroll
            for (int o2 = 0; o2 < 32; o2++) acc2[o2] = b2p[o2];
        }
#pragma unroll 1
        for (int j = 0; j < 128; j++) {
            ull s0 = 0ull, s1 = 0ull, s2 = 0ull, s3 = 0ull;  // 4 chains
            const ulonglong2* wr = (const ulonglong2*)(sm + OFF_W1 + j * 128);
#pragma unroll
            for (int k8 = 0; k8 < 16; k8++) {
                ulonglong2 a = wr[2*k8];
                ulonglong2 b = wr[2*k8 + 1];
                s0 = fma2(a.x, h2[4*k8],     s0);
                s1 = fma2(a.y, h2[4*k8 + 1], s1);
                s2 = fma2(b.x, h2[4*k8 + 2], s2);
                s3 = fma2(b.y, h2[4*k8 + 3], s3);
            }
            float2 f0 = unpack2(s0), f1 = unpack2(s1), f2 = unpack2(s2), f3 = unpack2(s3);
            float hj = sm[OFF_B1 + j] + (((f0.x + f0.y) + (f1.x + f1.y)) +
                                         ((f2.x + f2.y) + (f3.x + f3.y)));
            hj = fmaxf(hj, 0.0f);
            ull hj2 = pack2(hj, hj);
            const ulonglong2* w2r = (const ulonglong2*)(sm + OFF_W2T + j * 64);
#pragma unroll
            for (int o4 = 0; o4 < 16; o4++) {
                ulonglong2 wv = w2r[o4];
                acc2[2*o4]     = fma2(wv.x, hj2, acc2[2*o4]);
                acc2[2*o4 + 1] = fma2(wv.y, hj2, acc2[2*o4 + 1]);
            }
        }

        ulonglong2* op = (ulonglong2*)(out + (size_t)pt * 64);
#pragma unroll
        for (int o4 = 0; o4 < 16; o4++) {
            ulonglong2 v;
            v.x = acc2[2*o4];
            v.y = acc2[2*o4 + 1];
            op[o4] = v;
        }
    }
}

extern "C" void kernel_launch(void* const* d_in, const int* in_sizes, int n_in,
                              void* d_out, int out_size) {
    const float* pts = (const float*)d_in[0];
    const float* p0  = (const float*)d_in[1];
    const float* p1  = (const float*)d_in[2];
    const float* p2  = (const float*)d_in[3];
    const float* p3  = (const float*)d_in[4];
    const float* w0  = (const float*)d_in[5];
    const float* b0  = (const float*)d_in[6];
    const float* w1  = (const float*)d_in[7];
    const float* b1  = (const float*)d_in[8];
    const float* w2  = (const float*)d_in[9];
    const float* b2  = (const float*)d_in[10];

    int n = in_sizes[0] / 4;
    int ntiles = (n + 255) / 256;

    int sm_count = 148;
    cudaDeviceGetAttribute(&sm_count, cudaDevAttrMultiProcessorCount, 0);

    size_t smem_bytes = SMEM_FLOATS * sizeof(float);
    cudaFuncSetAttribute(fused_kernel, cudaFuncAttributeMaxDynamicSharedMemorySize,
                         (int)smem_bytes);

    prep_kernel<<<6912, 512>>>(p0, p1, p2, p3);
    fused_kernel<<<sm_count, 256, smem_bytes>>>(
        (const float4*)pts, w0, b0, w1, b1, w2, b2, (float*)d_out, n, ntiles);
}

// round 4
// speedup vs baseline: 3.1593x; 1.6147x over previous
#include <cuda_runtime.h>
#include <cstdint>

#define H_RES 150

// Transposed planes: per scale s (W = 64<<s), layout [3, H, W, 16].
__device__ __align__(16) float g_planes[6912000];

// ---- smem layout (floats) ----
// Wp (B-frag packed tf32): [0, 32768)   L0 @0 (2048 uint4-entries), L1 @8192, L2 @24576
// F  (feats, stride 68):   [32768, 41472)
// H  (per-warp 32x130):    [41472, 58112)
#define OFF_F   32768
#define OFF_H   41472
#define HW_STRIDE 4160          // 32*130 floats per warp
#define SM_BYTES 232448

__device__ __forceinline__ uint32_t tf32_of(float f) {
    uint32_t r;
    asm("cvt.rna.tf32.f32 %0, %1;" : "=r"(r) : "f"(f));
    return r;
}

__device__ __forceinline__ void mma8(float d[4], const uint32_t a[4], uint32_t b0, uint32_t b1) {
    asm volatile(
        "mma.sync.aligned.m16n8k8.row.col.f32.tf32.tf32.f32 "
        "{%0,%1,%2,%3}, {%4,%5,%6,%7}, {%8,%9}, {%0,%1,%2,%3};"
        : "+f"(d[0]), "+f"(d[1]), "+f"(d[2]), "+f"(d[3])
        : "r"(a[0]), "r"(a[1]), "r"(a[2]), "r"(a[3]), "r"(b0), "r"(b1));
}

// GEMM: [32 rows of A starting at rb] x W^T -> acc[2][NT][4].
// A: row-major tf32(uint32), stride as. Wp: fragment-packed ((k16*NT+n8)*32+lane) uint4.
template<int KC, int NT>
__device__ __forceinline__ void gemm(const uint32_t* __restrict__ A, int as, int rb,
                                     const uint4* __restrict__ Wp,
                                     int g, int q, int lane, float acc[2][NT][4]) {
#pragma unroll
    for (int mt = 0; mt < 2; mt++)
#pragma unroll
        for (int n8 = 0; n8 < NT; n8++)
#pragma unroll
            for (int i = 0; i < 4; i++) acc[mt][n8][i] = 0.f;

#pragma unroll 1
    for (int k16 = 0; k16 < KC; k16++) {
        uint32_t a[2][8];
        int c0 = k16 * 16 + q;
#pragma unroll
        for (int mt = 0; mt < 2; mt++) {
            int r0 = rb + mt * 16 + g;
            const uint32_t* lo = A + r0 * as;
            const uint32_t* hi = A + (r0 + 8) * as;
            a[mt][0] = lo[c0];      a[mt][1] = hi[c0];
            a[mt][2] = lo[c0 + 4];  a[mt][3] = hi[c0 + 4];
            a[mt][4] = lo[c0 + 8];  a[mt][5] = hi[c0 + 8];
            a[mt][6] = lo[c0 + 12]; a[mt][7] = hi[c0 + 12];
        }
        const uint4* W4 = Wp + (size_t)(k16 * NT) * 32 + lane;
#pragma unroll
        for (int n8 = 0; n8 < NT; n8++) {
            uint4 b = W4[n8 * 32];
            mma8(acc[0][n8], &a[0][0], b.x, b.y);
            mma8(acc[0][n8], &a[0][4], b.z, b.w);
            mma8(acc[1][n8], &a[1][0], b.x, b.y);
            mma8(acc[1][n8], &a[1][4], b.z, b.w);
        }
    }
}

// ---- prologue: transpose all 4 plane sets [3,16,150,W]->[3,150,W,16] ----
__global__ void prep_kernel(const float* __restrict__ p0, const float* __restrict__ p1,
                            const float* __restrict__ p2, const float* __restrict__ p3) {
    const int total = 6912000;
    for (int i = blockIdx.x * blockDim.x + threadIdx.x; i < total;
         i += gridDim.x * blockDim.x) {
        int s, base;
        const float* src;
        if (i < 460800)       { s = 0; base = 0;       src = p0; }
        else if (i < 1382400) { s = 1; base = 460800;  src = p1; }
        else if (i < 3225600) { s = 2; base = 1382400; src = p2; }
        else                  { s = 3; base = 3225600; src = p3; }
        int W = 64 << s;
        int li = i - base;
        int c = li & 15;
        int rest = li >> 4;
        int x = rest % W; rest /= W;
        int y = rest % H_RES;
        int p = rest / H_RES;
        g_planes[i] = src[((p * 16 + c) * H_RES + y) * W + x];
    }
}

// ---- persistent fused kernel: sample -> tf32 mma.sync MLP ----
__global__ void __launch_bounds__(128, 1) fused_kernel(
    const float4* __restrict__ pts,
    const float*  __restrict__ w0, const float* __restrict__ b0,
    const float*  __restrict__ w1, const float* __restrict__ b1,
    const float*  __restrict__ w2, const float* __restrict__ b2,
    float*        __restrict__ out, int n, int ntiles)
{
    extern __shared__ uint32_t sm[];
    const int tid  = threadIdx.x;
    const int lane = tid & 31;
    const int g    = lane >> 2;   // group id (row within m16 half)
    const int q    = lane & 3;    // thread in group (k / n*2 index)
    const int wrp  = tid >> 5;

    // ---- stage weights once: fragment-packed tf32 ----
    // entry e -> (layer, k16, n8, lane); 4 floats = {b0,b1 of k8a, b0,b1 of k8b}
    for (int e = tid; e < 8192; e += 128) {
        const float* W; int K, nt, base, le;
        if (e < 2048)      { W = w0; K = 64;  nt = 16; base = 0;     le = e; }
        else if (e < 6144) { W = w1; K = 128; nt = 16; base = 8192;  le = e - 2048; }
        else               { W = w2; K = 128; nt = 8;  base = 24576; le = e - 6144; }
        int perk = nt * 32;
        int k16 = le / perk;
        int r   = le % perk;
        int n8  = r >> 5;
        int ln  = r & 31;
        int nrow = n8 * 8 + (ln >> 2);
        int kb   = k16 * 16 + (ln & 3);
        const float* src = W + nrow * K + kb;
        uint4 v = { tf32_of(src[0]), tf32_of(src[4]), tf32_of(src[8]), tf32_of(src[12]) };
        ((uint4*)(sm + base))[le] = v;
    }
    __syncthreads();

    uint32_t* F  = sm + OFF_F;                       // [128][68]
    uint32_t* Hw = sm + OFF_H + wrp * HW_STRIDE;     // [32][130] per warp
    const uint4* Wp0 = (const uint4*)(sm);
    const uint4* Wp1 = (const uint4*)(sm + 8192);
    const uint4* Wp2 = (const uint4*)(sm + 24576);

    const int scale_off[4] = {0, 460800, 1382400, 3225600};

    for (int t = blockIdx.x; t < ntiles; t += gridDim.x) {
        const int pt = t * 128 + tid;

        // ---- 1. sampling: 1 thread = 1 point -> tf32 feats into F[tid][0..63] ----
        if (pt < n) {
            float4 P = pts[pt];
            float fy = (P.w + 1.0f) * 0.5f * (float)(H_RES - 1);
            fy = fminf(fmaxf(fy, 0.0f), (float)(H_RES - 1));
            int   iy0 = (int)floorf(fy);
            int   iy1 = min(iy0 + 1, H_RES - 1);
            float wyv = fy - (float)iy0;
            float coord[3] = {P.x, P.y, P.z};

#pragma unroll
            for (int s = 0; s < 4; s++) {
                const int W = 64 << s;
                float prod[16];
#pragma unroll
                for (int c = 0; c < 16; c++) prod[c] = 1.0f;
#pragma unroll
                for (int p = 0; p < 3; p++) {
                    float x  = coord[p];
                    float fx = (x + 1.0f) * 0.5f * (float)(W - 1);
                    fx = fminf(fmaxf(fx, 0.0f), (float)(W - 1));
                    int   ix0 = (int)floorf(fx);
                    int   ix1 = min(ix0 + 1, W - 1);
                    float wx  = fx - (float)ix0;

                    const float* pb = g_planes + scale_off[s] + p * (H_RES * W * 16);
                    const float4* r00 = (const float4*)(pb + (iy0 * W + ix0) * 16);
                    const float4* r01 = (const float4*)(pb + (iy0 * W + ix1) * 16);
                    const float4* r10 = (const float4*)(pb + (iy1 * W + ix0) * 16);
                    const float4* r11 = (const float4*)(pb + (iy1 * W + ix1) * 16);

                    float w00 = (1.0f - wx) * (1.0f - wyv);
                    float w01 = wx * (1.0f - wyv);
                    float w10 = (1.0f - wx) * wyv;
                    float w11 = wx * wyv;
#pragma unroll
                    for (int qq = 0; qq < 4; qq++) {
                        float4 a = r00[qq], b = r01[qq], c4 = r10[qq], d = r11[qq];
                        prod[4*qq+0] *= a.x*w00 + b.x*w01 + c4.x*w10 + d.x*w11;
                        prod[4*qq+1] *= a.y*w00 + b.y*w01 + c4.y*w10 + d.y*w11;
                        prod[4*qq+2] *= a.z*w00 + b.z*w01 + c4.z*w10 + d.z*w11;
                        prod[4*qq+3] *= a.w*w00 + b.w*w01 + c4.w*w10 + d.w*w11;
                    }
                }
#pragma unroll
                for (int qq = 0; qq < 4; qq++) {
                    uint4 v = { tf32_of(prod[4*qq+0]), tf32_of(prod[4*qq+1]),
                                tf32_of(prod[4*qq+2]), tf32_of(prod[4*qq+3]) };
                    *(uint4*)(F + tid * 68 + s * 16 + qq * 4) = v;
                }
            }
        } else {
#pragma unroll
            for (int c = 0; c < 16; c++)
                *(uint4*)(F + tid * 68 + c * 4) = uint4{0, 0, 0, 0};
        }
        __syncwarp();

        // ---- 2. layer0: acc = F[warp rows] @ w0^T   (K=64 -> KC=4, NT=16) ----
        float acc[2][16][4];
        gemm<4, 16>(F, 68, wrp * 32, Wp0, g, q, lane, acc);
        __syncwarp();

        // ---- 3. epilogue0: H = tf32(relu(acc + b0)) ----
#pragma unroll
        for (int n8 = 0; n8 < 16; n8++) {
            int col = n8 * 8 + q * 2;
            float bb0 = __ldg(b0 + col), bb1 = __ldg(b0 + col + 1);
#pragma unroll
            for (int mt = 0; mt < 2; mt++) {
                int r0 = mt * 16 + g;
                uint2 v0 = { tf32_of(fmaxf(acc[mt][n8][0] + bb0, 0.f)),
                             tf32_of(fmaxf(acc[mt][n8][1] + bb1, 0.f)) };
                *(uint2*)(Hw + r0 * 130 + col) = v0;
                uint2 v1 = { tf32_of(fmaxf(acc[mt][n8][2] + bb0, 0.f)),
                             tf32_of(fmaxf(acc[mt][n8][3] + bb1, 0.f)) };
                *(uint2*)(Hw + (r0 + 8) * 130 + col) = v1;
            }
        }
        __syncwarp();

        // ---- 4. layer1: acc = H @ w1^T   (K=128 -> KC=8, NT=16) ----
        gemm<8, 16>(Hw, 130, 0, Wp1, g, q, lane, acc);
        __syncwarp();

        // ---- 5. epilogue1: H = tf32(relu(acc + b1)) (overwrite) ----
#pragma unroll
        for (int n8 = 0; n8 < 16; n8++) {
            int col = n8 * 8 + q * 2;
            float bb0 = __ldg(b1 + col), bb1 = __ldg(b1 + col + 1);
#pragma unroll
            for (int mt = 0; mt < 2; mt++) {
                int r0 = mt * 16 + g;
                uint2 v0 = { tf32_of(fmaxf(acc[mt][n8][0] + bb0, 0.f)),
                             tf32_of(fmaxf(acc[mt][n8][1] + bb1, 0.f)) };
                *(uint2*)(Hw + r0 * 130 + col) = v0;
                uint2 v1 = { tf32_of(fmaxf(acc[mt][n8][2] + bb0, 0.f)),
                             tf32_of(fmaxf(acc[mt][n8][3] + bb1, 0.f)) };
                *(uint2*)(Hw + (r0 + 8) * 130 + col) = v1;
            }
        }
        __syncwarp();

        // ---- 6. layer2: acc3 = H @ w2^T   (K=128 -> KC=8, NT=8) ----
        float acc3[2][8][4];
        gemm<8, 8>(Hw, 130, 0, Wp2, g, q, lane, acc3);

        // ---- 7. epilogue2: out = acc3 + b2 ----
        {
            int rowb = t * 128 + wrp * 32;
#pragma unroll
            for (int n8 = 0; n8 < 8; n8++) {
                int col = n8 * 8 + q * 2;
                float bb0 = __ldg(b2 + col), bb1 = __ldg(b2 + col + 1);
#pragma unroll
                for (int mt = 0; mt < 2; mt++) {
                    int r0 = rowb + mt * 16 + g;
                    if (r0 < n) {
                        float2 o = { acc3[mt][n8][0] + bb0, acc3[mt][n8][1] + bb1 };
                        *(float2*)(out + (size_t)r0 * 64 + col) = o;
                    }
                    if (r0 + 8 < n) {
                        float2 o = { acc3[mt][n8][2] + bb0, acc3[mt][n8][3] + bb1 };
                        *(float2*)(out + (size_t)(r0 + 8) * 64 + col) = o;
                    }
                }
            }
        }
        __syncwarp();
    }
}

extern "C" void kernel_launch(void* const* d_in, const int* in_sizes, int n_in,
                              void* d_out, int out_size) {
    const float* pts = (const float*)d_in[0];
    const float* p0  = (const float*)d_in[1];
    const float* p1  = (const float*)d_in[2];
    const float* p2  = (const float*)d_in[3];
    const float* p3  = (const float*)d_in[4];
    const float* w0  = (const float*)d_in[5];
    const float* b0  = (const float*)d_in[6];
    const float* w1  = (const float*)d_in[7];
    const float* b1  = (const float*)d_in[8];
    const float* w2  = (const float*)d_in[9];
    const float* b2  = (const float*)d_in[10];

    int n = in_sizes[0] / 4;
    int ntiles = (n + 127) / 128;

    int sm_count = 148;
    cudaDeviceGetAttribute(&sm_count, cudaDevAttrMultiProcessorCount, 0);

    cudaFuncSetAttribute(fused_kernel, cudaFuncAttributeMaxDynamicSharedMemorySize, SM_BYTES);

    prep_kernel<<<6912, 512>>>(p0, p1, p2, p3);
    fused_kernel<<<sm_count, 128, SM_BYTES>>>(
        (const float4*)pts, w0, b0, w1, b1, w2, b2, (float*)d_out, n, ntiles);
}

// round 5
// speedup vs baseline: 3.9355x; 1.2457x over previous
#include <cuda_runtime.h>
#include <cstdint>

#define H_RES 150

// Transposed planes: per scale s (W = 64<<s), layout [3, H, W, 16].
__device__ __align__(16) float g_planes[6912000];

// smem (floats): weights packed [0,32768); per-warp buf [16][132] at 32768 + wrp*2112
#define OFF_BUF   32768
#define BUF_STRIDE 132
#define BUF_FLOATS 2112
#define SM_BYTES  232448

__device__ __forceinline__ uint32_t tf32_of(float f) {
    uint32_t r;
    asm("cvt.rna.tf32.f32 %0, %1;" : "=r"(r) : "f"(f));
    return r;
}

__device__ __forceinline__ void mma8(float d[4], const uint32_t a[4], uint32_t b0, uint32_t b1) {
    asm volatile(
        "mma.sync.aligned.m16n8k8.row.col.f32.tf32.tf32.f32 "
        "{%0,%1,%2,%3}, {%4,%5,%6,%7}, {%8,%9}, {%0,%1,%2,%3};"
        : "+f"(d[0]), "+f"(d[1]), "+f"(d[2]), "+f"(d[3])
        : "r"(a[0]), "r"(a[1]), "r"(a[2]), "r"(a[3]), "r"(b0), "r"(b1));
}

// GEMM: A[16 x 16*KC] (stride BUF_STRIDE, tf32 bits) x W^T -> acc[NT][4].
// Wp fragment-packed: ((k16*NT + n8)*32 + lane) uint4.
template<int KC, int NT>
__device__ __forceinline__ void gemm16(const uint32_t* __restrict__ A,
                                       const uint4* __restrict__ Wp,
                                       int g, int q, int lane, float acc[NT][4]) {
#pragma unroll
    for (int n8 = 0; n8 < NT; n8++)
#pragma unroll
        for (int i = 0; i < 4; i++) acc[n8][i] = 0.f;

    const uint32_t* lo = A + g * BUF_STRIDE;
    const uint32_t* hi = A + (g + 8) * BUF_STRIDE;

#pragma unroll
    for (int k16 = 0; k16 < KC; k16++) {
        uint32_t a[8];
        int c0 = k16 * 16 + q;
        a[0] = lo[c0];      a[1] = hi[c0];
        a[2] = lo[c0 + 4];  a[3] = hi[c0 + 4];
        a[4] = lo[c0 + 8];  a[5] = hi[c0 + 8];
        a[6] = lo[c0 + 12]; a[7] = hi[c0 + 12];
        const uint4* W4 = Wp + (size_t)(k16 * NT) * 32 + lane;
#pragma unroll
        for (int n8 = 0; n8 < NT; n8++) {
            uint4 b = W4[n8 * 32];
            mma8(acc[n8], &a[0], b.x, b.y);
            mma8(acc[n8], &a[4], b.z, b.w);
        }
    }
}

// ---- prologue: transpose all 4 plane sets [3,16,150,W]->[3,150,W,16] ----
__global__ void prep_kernel(const float* __restrict__ p0, const float* __restrict__ p1,
                            const float* __restrict__ p2, const float* __restrict__ p3) {
    const int total = 6912000;
    for (int i = blockIdx.x * blockDim.x + threadIdx.x; i < total;
         i += gridDim.x * blockDim.x) {
        int s, base;
        const float* src;
        if (i < 460800)       { s = 0; base = 0;       src = p0; }
        else if (i < 1382400) { s = 1; base = 460800;  src = p1; }
        else if (i < 3225600) { s = 2; base = 1382400; src = p2; }
        else                  { s = 3; base = 3225600; src = p3; }
        int W = 64 << s;
        int li = i - base;
        int c = li & 15;
        int rest = li >> 4;
        int x = rest % W; rest /= W;
        int y = rest % H_RES;
        int p = rest / H_RES;
        g_planes[i] = src[((p * 16 + c) * H_RES + y) * W + x];
    }
}

// ---- persistent fused kernel: 12 independent warps, each owns m16 slices ----
__global__ void __launch_bounds__(384, 1) fused_kernel(
    const float4* __restrict__ pts,
    const float*  __restrict__ w0, const float* __restrict__ b0,
    const float*  __restrict__ w1, const float* __restrict__ b1,
    const float*  __restrict__ w2, const float* __restrict__ b2,
    float*        __restrict__ out, int n, int ntiles)
{
    extern __shared__ uint32_t sm[];
    const int tid  = threadIdx.x;
    const int lane = tid & 31;
    const int g    = lane >> 2;
    const int q    = lane & 3;
    const int wrp  = tid >> 5;

    // ---- stage weights once: fragment-packed tf32 (same scheme as R4, verified) ----
    for (int e = tid; e < 8192; e += 384) {
        const float* W; int K, nt, base, le;
        if (e < 2048)      { W = w0; K = 64;  nt = 16; base = 0;     le = e; }
        else if (e < 6144) { W = w1; K = 128; nt = 16; base = 8192;  le = e - 2048; }
        else               { W = w2; K = 128; nt = 8;  base = 24576; le = e - 6144; }
        int perk = nt * 32;
        int k16 = le / perk;
        int r   = le % perk;
        int n8  = r >> 5;
        int ln  = r & 31;
        int nrow = n8 * 8 + (ln >> 2);
        int kb   = k16 * 16 + (ln & 3);
        const float* src = W + nrow * K + kb;
        uint4 v = { tf32_of(src[0]), tf32_of(src[4]), tf32_of(src[8]), tf32_of(src[12]) };
        ((uint4*)(sm + base))[le] = v;
    }
    __syncthreads();

    uint32_t* buf = sm + OFF_BUF + wrp * BUF_FLOATS;   // per-warp [16][132]
    const uint4* Wp0 = (const uint4*)(sm);
    const uint4* Wp1 = (const uint4*)(sm + 8192);
    const uint4* Wp2 = (const uint4*)(sm + 24576);

    const int scale_off[4] = {0, 460800, 1382400, 3225600};

    const int pr     = lane & 15;          // point row within warp slice
    const int s_base = (lane >> 4) << 1;   // scales {0,1} or {2,3}

    for (int t = blockIdx.x; t < ntiles; t += gridDim.x) {
        const int rowb = t * 192 + wrp * 16;

        // ---- 1. sampling: 2 threads per point (2 scales x 3 planes each) ----
        {
            int pt  = rowb + pr;
            int ptc = min(pt, n - 1);
            float4 P = pts[ptc];
            float fy = (P.w + 1.0f) * 0.5f * (float)(H_RES - 1);
            fy = fminf(fmaxf(fy, 0.0f), (float)(H_RES - 1));
            int   iy0 = (int)floorf(fy);
            int   iy1 = min(iy0 + 1, H_RES - 1);
            float wyv = fy - (float)iy0;
            float coord[3] = {P.x, P.y, P.z};

#pragma unroll
            for (int si = 0; si < 2; si++) {
                const int s = s_base + si;
                const int W = 64 << s;
                float prod[16];
#pragma unroll
                for (int c = 0; c < 16; c++) prod[c] = 1.0f;
#pragma unroll
                for (int p = 0; p < 3; p++) {
                    float x  = coord[p];
                    float fx = (x + 1.0f) * 0.5f * (float)(W - 1);
                    fx = fminf(fmaxf(fx, 0.0f), (float)(W - 1));
                    int   ix0 = (int)floorf(fx);
                    int   ix1 = min(ix0 + 1, W - 1);
                    float wx  = fx - (float)ix0;

                    const float* pb = g_planes + scale_off[s] + p * (H_RES * W * 16);
                    const float4* r00 = (const float4*)(pb + (iy0 * W + ix0) * 16);
                    const float4* r01 = (const float4*)(pb + (iy0 * W + ix1) * 16);
                    const float4* r10 = (const float4*)(pb + (iy1 * W + ix0) * 16);
                    const float4* r11 = (const float4*)(pb + (iy1 * W + ix1) * 16);

                    float w00 = (1.0f - wx) * (1.0f - wyv);
                    float w01 = wx * (1.0f - wyv);
                    float w10 = (1.0f - wx) * wyv;
                    float w11 = wx * wyv;
#pragma unroll
                    for (int qq = 0; qq < 4; qq++) {
                        float4 a = r00[qq], b = r01[qq], c4 = r10[qq], d = r11[qq];
                        prod[4*qq+0] *= a.x*w00 + b.x*w01 + c4.x*w10 + d.x*w11;
                        prod[4*qq+1] *= a.y*w00 + b.y*w01 + c4.y*w10 + d.y*w11;
                        prod[4*qq+2] *= a.z*w00 + b.z*w01 + c4.z*w10 + d.z*w11;
                        prod[4*qq+3] *= a.w*w00 + b.w*w01 + c4.w*w10 + d.w*w11;
                    }
                }
#pragma unroll
                for (int qq = 0; qq < 4; qq++) {
                    uint4 v = { tf32_of(prod[4*qq+0]), tf32_of(prod[4*qq+1]),
                                tf32_of(prod[4*qq+2]), tf32_of(prod[4*qq+3]) };
                    *(uint4*)(buf + pr * BUF_STRIDE + s * 16 + qq * 4) = v;
                }
            }
        }
        __syncwarp();

        // ---- 2. layer0: acc = F @ w0^T  (K=64) ----
        float acc[16][4];
        gemm16<4, 16>(buf, Wp0, g, q, lane, acc);
        __syncwarp();

        // ---- 3. epilogue0: H = tf32(relu(acc + b0)), overwrite buf ----
#pragma unroll
        for (int n8 = 0; n8 < 16; n8++) {
            int col = n8 * 8 + q * 2;
            float bb0 = __ldg(b0 + col), bb1 = __ldg(b0 + col + 1);
            uint2 v0 = { tf32_of(fmaxf(acc[n8][0] + bb0, 0.f)),
                         tf32_of(fmaxf(acc[n8][1] + bb1, 0.f)) };
            *(uint2*)(buf + g * BUF_STRIDE + col) = v0;
            uint2 v1 = { tf32_of(fmaxf(acc[n8][2] + bb0, 0.f)),
                         tf32_of(fmaxf(acc[n8][3] + bb1, 0.f)) };
            *(uint2*)(buf + (g + 8) * BUF_STRIDE + col) = v1;
        }
        __syncwarp();

        // ---- 4. layer1: acc = H @ w1^T  (K=128) ----
        gemm16<8, 16>(buf, Wp1, g, q, lane, acc);
        __syncwarp();

        // ---- 5. epilogue1: H = tf32(relu(acc + b1)) ----
#pragma unroll
        for (int n8 = 0; n8 < 16; n8++) {
            int col = n8 * 8 + q * 2;
            float bb0 = __ldg(b1 + col), bb1 = __ldg(b1 + col + 1);
            uint2 v0 = { tf32_of(fmaxf(acc[n8][0] + bb0, 0.f)),
                         tf32_of(fmaxf(acc[n8][1] + bb1, 0.f)) };
            *(uint2*)(buf + g * BUF_STRIDE + col) = v0;
            uint2 v1 = { tf32_of(fmaxf(acc[n8][2] + bb0, 0.f)),
                         tf32_of(fmaxf(acc[n8][3] + bb1, 0.f)) };
            *(uint2*)(buf + (g + 8) * BUF_STRIDE + col) = v1;
        }
        __syncwarp();

        // ---- 6. layer2: acc3 = H @ w2^T  (K=128, N=64) + output ----
        float acc3[8][4];
        gemm16<8, 8>(buf, Wp2, g, q, lane, acc3);

#pragma unroll
        for (int n8 = 0; n8 < 8; n8++) {
            int col = n8 * 8 + q * 2;
            float bb0 = __ldg(b2 + col), bb1 = __ldg(b2 + col + 1);
            int r0 = rowb + g;
            if (r0 < n) {
                float2 o = { acc3[n8][0] + bb0, acc3[n8][1] + bb1 };
                *(float2*)(out + (size_t)r0 * 64 + col) = o;
            }
            if (r0 + 8 < n) {
                float2 o = { acc3[n8][2] + bb0, acc3[n8][3] + bb1 };
                *(float2*)(out + (size_t)(r0 + 8) * 64 + col) = o;
            }
        }
        __syncwarp();
    }
}

extern "C" void kernel_launch(void* const* d_in, const int* in_sizes, int n_in,
                              void* d_out, int out_size) {
    const float* pts = (const float*)d_in[0];
    const float* p0  = (const float*)d_in[1];
    const float* p1  = (const float*)d_in[2];
    const float* p2  = (const float*)d_in[3];
    const float* p3  = (const float*)d_in[4];
    const float* w0  = (const float*)d_in[5];
    const float* b0  = (const float*)d_in[6];
    const float* w1  = (const float*)d_in[7];
    const float* b1  = (const float*)d_in[8];
    const float* w2  = (const float*)d_in[9];
    const float* b2  = (const float*)d_in[10];

    int n = in_sizes[0] / 4;
    int ntiles = (n + 191) / 192;

    int sm_count = 148;
    cudaDeviceGetAttribute(&sm_count, cudaDevAttrMultiProcessorCount, 0);

    cudaFuncSetAttribute(fused_kernel, cudaFuncAttributeMaxDynamicSharedMemorySize, SM_BYTES);

    prep_kernel<<<6912, 512>>>(p0, p1, p2, p3);
    fused_kernel<<<sm_count, 384, SM_BYTES>>>(
        (const float4*)pts, w0, b0, w1, b1, w2, b2, (float*)d_out, n, ntiles);
}

// round 6
// speedup vs baseline: 6.0506x; 1.5374x over previous
#include <cuda_runtime.h>
#include <cuda_fp16.h>
#include <cstdint>

#define H_RES 150

// Transposed planes: per scale s (W = 64<<s), layout [3, H, W, 16].
__device__ __align__(16) float g_planes[6912000];

// smem (uint32 words): fp16 weights [0,16384); per-warp buf [16][68] at 16384+wrp*1088
#define OFF_BUF    16384
#define BUF_STRIDE 68
#define BUF_WORDS  1088
#define SM_BYTES   135168

__device__ __forceinline__ uint32_t h2_of(float a, float b) {
    __half2 h = __float22half2_rn(make_float2(a, b));   // .x = low half
    return *(uint32_t*)&h;
}

__device__ __forceinline__ void mma16(float d[4], uint32_t a0, uint32_t a1,
                                      uint32_t a2, uint32_t a3,
                                      uint32_t b0, uint32_t b1) {
    asm volatile(
        "mma.sync.aligned.m16n8k16.row.col.f32.f16.f16.f32 "
        "{%0,%1,%2,%3}, {%4,%5,%6,%7}, {%8,%9}, {%0,%1,%2,%3};"
        : "+f"(d[0]), "+f"(d[1]), "+f"(d[2]), "+f"(d[3])
        : "r"(a0), "r"(a1), "r"(a2), "r"(a3), "r"(b0), "r"(b1));
}

// GEMM: A[16 x 16*KC] fp16 (word stride BUF_STRIDE) x W^T -> acc[NT][4].
// Wp fragment-packed uint2: ((k16*NT + n8)*32 + lane).
template<int KC, int NT>
__device__ __forceinline__ void gemm16(const uint32_t* __restrict__ A,
                                       const uint2* __restrict__ Wp,
                                       int g, int q, int lane, float acc[NT][4]) {
#pragma unroll
    for (int n8 = 0; n8 < NT; n8++)
#pragma unroll
        for (int i = 0; i < 4; i++) acc[n8][i] = 0.f;

    const uint32_t* lo = A + g * BUF_STRIDE;
    const uint32_t* hi = A + (g + 8) * BUF_STRIDE;

#pragma unroll
    for (int k16 = 0; k16 < KC; k16++) {
        int cw = k16 * 8 + q;
        uint32_t a0 = lo[cw], a1 = hi[cw], a2 = lo[cw + 4], a3 = hi[cw + 4];
        const uint2* W2 = Wp + (size_t)(k16 * NT) * 32 + lane;
#pragma unroll
        for (int n8 = 0; n8 < NT; n8++) {
            uint2 b = W2[n8 * 32];
            mma16(acc[n8], a0, a1, a2, a3, b.x, b.y);
        }
    }
}

// ---- prologue: transpose all 4 plane sets [3,16,150,W]->[3,150,W,16] ----
__global__ void prep_kernel(const float* __restrict__ p0, const float* __restrict__ p1,
                            const float* __restrict__ p2, const float* __restrict__ p3) {
    const int total = 6912000;
    for (int i = blockIdx.x * blockDim.x + threadIdx.x; i < total;
         i += gridDim.x * blockDim.x) {
        int s, base;
        const float* src;
        if (i < 460800)       { s = 0; base = 0;       src = p0; }
        else if (i < 1382400) { s = 1; base = 460800;  src = p1; }
        else if (i < 3225600) { s = 2; base = 1382400; src = p2; }
        else                  { s = 3; base = 3225600; src = p3; }
        int W = 64 << s;
        int li = i - base;
        int c = li & 15;
        int rest = li >> 4;
        int x = rest % W; rest /= W;
        int y = rest % H_RES;
        int p = rest / H_RES;
        g_planes[i] = src[((p * 16 + c) * H_RES + y) * W + x];
    }
}

// ---- persistent fused kernel: 16 independent warps, each owns m16 slices ----
__global__ void __launch_bounds__(512, 1) fused_kernel(
    const float4* __restrict__ pts,
    const float*  __restrict__ w0, const float* __restrict__ b0,
    const float*  __restrict__ w1, const float* __restrict__ b1,
    const float*  __restrict__ w2, const float* __restrict__ b2,
    float*        __restrict__ out, int n, int ntiles)
{
    extern __shared__ uint32_t sm[];
    const int tid  = threadIdx.x;
    const int lane = tid & 31;
    const int g    = lane >> 2;
    const int q    = lane & 3;
    const int wrp  = tid >> 5;

    // ---- stage fp16 weights once, fragment-packed uint2 ----
    // b0 = {W[n][k], W[n][k+1]}, b1 = {W[n][k+8], W[n][k+9]}, n = n8*8+g, k = k16*16+2q
    for (int e = tid; e < 8192; e += 512) {
        const float* W; int K, nt, le;
        if (e < 2048)      { W = w0; K = 64;  nt = 16; le = e; }
        else if (e < 6144) { W = w1; K = 128; nt = 16; le = e - 2048; }
        else               { W = w2; K = 128; nt = 8;  le = e - 6144; }
        int perk = nt * 32;
        int k16 = le / perk;
        int r   = le % perk;
        int n8  = r >> 5;
        int ln  = r & 31;
        int nrow = n8 * 8 + (ln >> 2);
        int kb   = k16 * 16 + 2 * (ln & 3);
        const float* src = W + nrow * K + kb;
        uint2 v = { h2_of(src[0], src[1]), h2_of(src[8], src[9]) };
        ((uint2*)sm)[e] = v;
    }
    __syncthreads();

    uint32_t* buf = sm + OFF_BUF + wrp * BUF_WORDS;   // per-warp [16][68] fp16-words
    const uint2* Wp0 = (const uint2*)sm;
    const uint2* Wp1 = (const uint2*)sm + 2048;
    const uint2* Wp2 = (const uint2*)sm + 6144;

    const int scale_off[4] = {0, 460800, 1382400, 3225600};

    const int pr     = lane & 15;          // point row within warp slice
    const int s_base = (lane >> 4) << 1;   // scales {0,1} or {2,3}

    for (int t = blockIdx.x; t < ntiles; t += gridDim.x) {
        const int rowb = t * 256 + wrp * 16;

        // ---- 1. sampling: 2 threads per point (2 scales x 3 planes each) ----
        {
            int pt  = rowb + pr;
            int ptc = min(pt, n - 1);
            float4 P = pts[ptc];
            float fy = (P.w + 1.0f) * 0.5f * (float)(H_RES - 1);
            fy = fminf(fmaxf(fy, 0.0f), (float)(H_RES - 1));
            int   iy0 = (int)floorf(fy);
            int   iy1 = min(iy0 + 1, H_RES - 1);
            float wyv = fy - (float)iy0;
            float coord[3] = {P.x, P.y, P.z};

#pragma unroll
            for (int si = 0; si < 2; si++) {
                const int s = s_base + si;
                const int W = 64 << s;
                float prod[16];
#pragma unroll
                for (int c = 0; c < 16; c++) prod[c] = 1.0f;
#pragma unroll
                for (int p = 0; p < 3; p++) {
                    float x  = coord[p];
                    float fx = (x + 1.0f) * 0.5f * (float)(W - 1);
                    fx = fminf(fmaxf(fx, 0.0f), (float)(W - 1));
                    int   ix0 = (int)floorf(fx);
                    int   ix1 = min(ix0 + 1, W - 1);
                    float wx  = fx - (float)ix0;

                    const float* pb = g_planes + scale_off[s] + p * (H_RES * W * 16);
                    const float4* r00 = (const float4*)(pb + (iy0 * W + ix0) * 16);
                    const float4* r01 = (const float4*)(pb + (iy0 * W + ix1) * 16);
                    const float4* r10 = (const float4*)(pb + (iy1 * W + ix0) * 16);
                    const float4* r11 = (const float4*)(pb + (iy1 * W + ix1) * 16);

                    float w00 = (1.0f - wx) * (1.0f - wyv);
                    float w01 = wx * (1.0f - wyv);
                    float w10 = (1.0f - wx) * wyv;
                    float w11 = wx * wyv;
#pragma unroll
                    for (int qq = 0; qq < 4; qq++) {
                        float4 a = r00[qq], b = r01[qq], c4 = r10[qq], d = r11[qq];
                        prod[4*qq+0] *= a.x*w00 + b.x*w01 + c4.x*w10 + d.x*w11;
                        prod[4*qq+1] *= a.y*w00 + b.y*w01 + c4.y*w10 + d.y*w11;
                        prod[4*qq+2] *= a.z*w00 + b.z*w01 + c4.z*w10 + d.z*w11;
                        prod[4*qq+3] *= a.w*w00 + b.w*w01 + c4.w*w10 + d.w*w11;
                    }
                }
                // fp16 feats: 16 floats -> 8 half2 words -> 2 uint4 stores
                uint4 v0 = { h2_of(prod[0],  prod[1]),  h2_of(prod[2],  prod[3]),
                             h2_of(prod[4],  prod[5]),  h2_of(prod[6],  prod[7]) };
                uint4 v1 = { h2_of(prod[8],  prod[9]),  h2_of(prod[10], prod[11]),
                             h2_of(prod[12], prod[13]), h2_of(prod[14], prod[15]) };
                *(uint4*)(buf + pr * BUF_STRIDE + s * 8)     = v0;
                *(uint4*)(buf + pr * BUF_STRIDE + s * 8 + 4) = v1;
            }
        }
        __syncwarp();

        // ---- 2. layer0: acc = F @ w0^T  (K=64 -> KC=4) ----
        float acc[16][4];
        gemm16<4, 16>(buf, Wp0, g, q, lane, acc);
        __syncwarp();

        // ---- 3. epilogue0: H = fp16(relu(acc + b0)), overwrite buf ----
#pragma unroll
        for (int n8 = 0; n8 < 16; n8++) {
            int col = n8 * 8 + 2 * q;
            int w   = n8 * 4 + q;
            float bb0 = __ldg(b0 + col), bb1 = __ldg(b0 + col + 1);
            buf[g * BUF_STRIDE + w] =
                h2_of(fmaxf(acc[n8][0] + bb0, 0.f), fmaxf(acc[n8][1] + bb1, 0.f));
            buf[(g + 8) * BUF_STRIDE + w] =
                h2_of(fmaxf(acc[n8][2] + bb0, 0.f), fmaxf(acc[n8][3] + bb1, 0.f));
        }
        __syncwarp();

        // ---- 4. layer1: acc = H @ w1^T  (K=128 -> KC=8) ----
        gemm16<8, 16>(buf, Wp1, g, q, lane, acc);
        __syncwarp();

        // ---- 5. epilogue1: H = fp16(relu(acc + b1)) ----
#pragma unroll
        for (int n8 = 0; n8 < 16; n8++) {
            int col = n8 * 8 + 2 * q;
            int w   = n8 * 4 + q;
            float bb0 = __ldg(b1 + col), bb1 = __ldg(b1 + col + 1);
            buf[g * BUF_STRIDE + w] =
                h2_of(fmaxf(acc[n8][0] + bb0, 0.f), fmaxf(acc[n8][1] + bb1, 0.f));
            buf[(g + 8) * BUF_STRIDE + w] =
                h2_of(fmaxf(acc[n8][2] + bb0, 0.f), fmaxf(acc[n8][3] + bb1, 0.f));
        }
        __syncwarp();

        // ---- 6. layer2: acc3 = H @ w2^T  (K=128, N=64) + output ----
        float acc3[8][4];
        gemm16<8, 8>(buf, Wp2, g, q, lane, acc3);

#pragma unroll
        for (int n8 = 0; n8 < 8; n8++) {
            int col = n8 * 8 + 2 * q;
            float bb0 = __ldg(b2 + col), bb1 = __ldg(b2 + col + 1);
            int r0 = rowb + g;
            if (r0 < n) {
                float2 o = { acc3[n8][0] + bb0, acc3[n8][1] + bb1 };
                *(float2*)(out + (size_t)r0 * 64 + col) = o;
            }
            if (r0 + 8 < n) {
                float2 o = { acc3[n8][2] + bb0, acc3[n8][3] + bb1 };
                *(float2*)(out + (size_t)(r0 + 8) * 64 + col) = o;
            }
        }
        __syncwarp();
    }
}

extern "C" void kernel_launch(void* const* d_in, const int* in_sizes, int n_in,
                              void* d_out, int out_size) {
    const float* pts = (const float*)d_in[0];
    const float* p0  = (const float*)d_in[1];
    const float* p1  = (const float*)d_in[2];
    const float* p2  = (const float*)d_in[3];
    const float* p3  = (const float*)d_in[4];
    const float* w0  = (const float*)d_in[5];
    const float* b0  = (const float*)d_in[6];
    const float* w1  = (const float*)d_in[7];
    const float* b1  = (const float*)d_in[8];
    const float* w2  = (const float*)d_in[9];
    const float* b2  = (const float*)d_in[10];

    int n = in_sizes[0] / 4;
    int ntiles = (n + 255) / 256;

    int sm_count = 148;
    cudaDeviceGetAttribute(&sm_count, cudaDevAttrMultiProcessorCount, 0);

    cudaFuncSetAttribute(fused_kernel, cudaFuncAttributeMaxDynamicSharedMemorySize, SM_BYTES);

    prep_kernel<<<6912, 512>>>(p0, p1, p2, p3);
    fused_kernel<<<sm_count, 512, SM_BYTES>>>(
        (const float4*)pts, w0, b0, w1, b1, w2, b2, (float*)d_out, n, ntiles);
}

// round 7
// speedup vs baseline: 11.3833x; 1.8813x over previous
#include <cuda_runtime.h>
#include <cuda_fp16.h>
#include <cstdint>

#define H_RES 150

// Transposed planes: per scale s (W = 64<<s), layout [3, H, W, 16].
__device__ __align__(16) float g_planes[6912000];

// smem (uint32 words): fp16 weights [0,16384); per-warp buf [16][68] at 16384+wrp*1088
#define OFF_BUF    16384
#define BUF_STRIDE 68
#define BUF_WORDS  1088
#define SM_BYTES   135168

__device__ __forceinline__ uint32_t h2_of(float a, float b) {
    __half2 h = __float22half2_rn(make_float2(a, b));   // .x = low half
    return *(uint32_t*)&h;
}

__device__ __forceinline__ void mma16(float d[4], uint32_t a0, uint32_t a1,
                                      uint32_t a2, uint32_t a3,
                                      uint32_t b0, uint32_t b1) {
    asm volatile(
        "mma.sync.aligned.m16n8k16.row.col.f32.f16.f16.f32 "
        "{%0,%1,%2,%3}, {%4,%5,%6,%7}, {%8,%9}, {%0,%1,%2,%3};"
        : "+f"(d[0]), "+f"(d[1]), "+f"(d[2]), "+f"(d[3])
        : "r"(a0), "r"(a1), "r"(a2), "r"(a3), "r"(b0), "r"(b1));
}

// GEMM: A[16 x 16*KC] fp16 (word stride BUF_STRIDE) x W^T -> acc[NT][4].
// Wp fragment-packed uint2: ((k16*NT + n8)*32 + lane).
template<int KC, int NT>
__device__ __forceinline__ void gemm16(const uint32_t* __restrict__ A,
                                       const uint2* __restrict__ Wp,
                                       int g, int q, int lane, float acc[NT][4]) {
#pragma unroll
    for (int n8 = 0; n8 < NT; n8++)
#pragma unroll
        for (int i = 0; i < 4; i++) acc[n8][i] = 0.f;

    const uint32_t* lo = A + g * BUF_STRIDE;
    const uint32_t* hi = A + (g + 8) * BUF_STRIDE;

#pragma unroll
    for (int k16 = 0; k16 < KC; k16++) {
        int cw = k16 * 8 + q;
        uint32_t a0 = lo[cw], a1 = hi[cw], a2 = lo[cw + 4], a3 = hi[cw + 4];
        const uint2* W2 = Wp + (size_t)(k16 * NT) * 32 + lane;
#pragma unroll
        for (int n8 = 0; n8 < NT; n8++) {
            uint2 b = W2[n8 * 32];
            mma16(acc[n8], a0, a1, a2, a3, b.x, b.y);
        }
    }
}

// ---- prologue: transpose all 4 plane sets [3,16,150,W]->[3,150,W,16] ----
__global__ void prep_kernel(const float* __restrict__ p0, const float* __restrict__ p1,
                            const float* __restrict__ p2, const float* __restrict__ p3) {
    const int total = 6912000;
    for (int i = blockIdx.x * blockDim.x + threadIdx.x; i < total;
         i += gridDim.x * blockDim.x) {
        int s, base;
        const float* src;
        if (i < 460800)       { s = 0; base = 0;       src = p0; }
        else if (i < 1382400) { s = 1; base = 460800;  src = p1; }
        else if (i < 3225600) { s = 2; base = 1382400; src = p2; }
        else                  { s = 3; base = 3225600; src = p3; }
        int W = 64 << s;
        int li = i - base;
        int c = li & 15;
        int rest = li >> 4;
        int x = rest % W; rest /= W;
        int y = rest % H_RES;
        int p = rest / H_RES;
        g_planes[i] = src[((p * 16 + c) * H_RES + y) * W + x];
    }
}

// ---- persistent fused kernel: 16 independent warps, each owns m16 slices ----
__global__ void __launch_bounds__(512, 1) fused_kernel(
    const float4* __restrict__ pts,
    const float*  __restrict__ w0, const float* __restrict__ b0,
    const float*  __restrict__ w1, const float* __restrict__ b1,
    const float*  __restrict__ w2, const float* __restrict__ b2,
    float*        __restrict__ out, int n, int ntiles)
{
    extern __shared__ uint32_t sm[];
    const int tid  = threadIdx.x;
    const int lane = tid & 31;
    const int g    = lane >> 2;
    const int q    = lane & 3;
    const int wrp  = tid >> 5;

    // ---- stage fp16 weights once, fragment-packed uint2 ----
    for (int e = tid; e < 8192; e += 512) {
        const float* W; int K, nt, le;
        if (e < 2048)      { W = w0; K = 64;  nt = 16; le = e; }
        else if (e < 6144) { W = w1; K = 128; nt = 16; le = e - 2048; }
        else               { W = w2; K = 128; nt = 8;  le = e - 6144; }
        int perk = nt * 32;
        int k16 = le / perk;
        int r   = le % perk;
        int n8  = r >> 5;
        int ln  = r & 31;
        int nrow = n8 * 8 + (ln >> 2);
        int kb   = k16 * 16 + 2 * (ln & 3);
        const float* src = W + nrow * K + kb;
        uint2 v = { h2_of(src[0], src[1]), h2_of(src[8], src[9]) };
        ((uint2*)sm)[e] = v;
    }
    __syncthreads();

    uint32_t* buf = sm + OFF_BUF + wrp * BUF_WORDS;   // per-warp [16][68] fp16-words
    const uint2* Wp0 = (const uint2*)sm;
    const uint2* Wp1 = (const uint2*)sm + 2048;
    const uint2* Wp2 = (const uint2*)sm + 6144;

    const int scale_off[4] = {0, 460800, 1382400, 3225600};

    const int ch4  = lane & 3;    // channel chunk (4 channels)
    const int pidx = lane >> 2;   // point index within pass (0..7)

    for (int t = blockIdx.x; t < ntiles; t += gridDim.x) {
        const int rowb = t * 256 + wrp * 16;

        // ---- 1. sampling: lane-cooperative — 4 lanes per point, 1 corner = 1 line ----
#pragma unroll
        for (int pass = 0; pass < 2; pass++) {
            const int pr = pass * 8 + pidx;
            int ptc = min(rowb + pr, n - 1);
            float4 P = pts[ptc];

            float fy = (P.w + 1.0f) * 0.5f * (float)(H_RES - 1);
            fy = fminf(fmaxf(fy, 0.0f), (float)(H_RES - 1));
            int   iy0 = (int)floorf(fy);
            int   iy1 = min(iy0 + 1, H_RES - 1);
            float wyv = fy - (float)iy0;
            float coord[3] = {P.x, P.y, P.z};

#pragma unroll
            for (int s = 0; s < 4; s++) {
                const int W = 64 << s;
                float prod[4] = {1.f, 1.f, 1.f, 1.f};
#pragma unroll
                for (int p = 0; p < 3; p++) {
                    float x  = coord[p];
                    float fx = (x + 1.0f) * 0.5f * (float)(W - 1);
                    fx = fminf(fmaxf(fx, 0.0f), (float)(W - 1));
                    int   ix0 = (int)floorf(fx);
                    int   ix1 = min(ix0 + 1, W - 1);
                    float wx  = fx - (float)ix0;

                    const float4* pb4 = (const float4*)(g_planes + scale_off[s]
                                                        + p * (H_RES * W * 16));
                    float4 a = pb4[(iy0 * W + ix0) * 4 + ch4];
                    float4 b = pb4[(iy0 * W + ix1) * 4 + ch4];
                    float4 c = pb4[(iy1 * W + ix0) * 4 + ch4];
                    float4 d = pb4[(iy1 * W + ix1) * 4 + ch4];

                    float w00 = (1.0f - wx) * (1.0f - wyv);
                    float w01 = wx * (1.0f - wyv);
                    float w10 = (1.0f - wx) * wyv;
                    float w11 = wx * wyv;

                    prod[0] *= a.x*w00 + b.x*w01 + c.x*w10 + d.x*w11;
                    prod[1] *= a.y*w00 + b.y*w01 + c.y*w10 + d.y*w11;
                    prod[2] *= a.z*w00 + b.z*w01 + c.z*w10 + d.z*w11;
                    prod[3] *= a.w*w00 + b.w*w01 + c.w*w10 + d.w*w11;
                }
                uint2 v = { h2_of(prod[0], prod[1]), h2_of(prod[2], prod[3]) };
                *(uint2*)(buf + pr * BUF_STRIDE + s * 8 + ch4 * 2) = v;
            }
        }
        __syncwarp();

        // ---- 2. layer0: acc = F @ w0^T  (K=64 -> KC=4) ----
        float acc[16][4];
        gemm16<4, 16>(buf, Wp0, g, q, lane, acc);
        __syncwarp();

        // ---- 3. epilogue0: H = fp16(relu(acc + b0)), overwrite buf ----
#pragma unroll
        for (int n8 = 0; n8 < 16; n8++) {
            int col = n8 * 8 + 2 * q;
            int w   = n8 * 4 + q;
            float bb0 = __ldg(b0 + col), bb1 = __ldg(b0 + col + 1);
            buf[g * BUF_STRIDE + w] =
                h2_of(fmaxf(acc[n8][0] + bb0, 0.f), fmaxf(acc[n8][1] + bb1, 0.f));
            buf[(g + 8) * BUF_STRIDE + w] =
                h2_of(fmaxf(acc[n8][2] + bb0, 0.f), fmaxf(acc[n8][3] + bb1, 0.f));
        }
        __syncwarp();

        // ---- 4. layer1: acc = H @ w1^T  (K=128 -> KC=8) ----
        gemm16<8, 16>(buf, Wp1, g, q, lane, acc);
        __syncwarp();

        // ---- 5. epilogue1: H = fp16(relu(acc + b1)) ----
#pragma unroll
        for (int n8 = 0; n8 < 16; n8++) {
            int col = n8 * 8 + 2 * q;
            int w   = n8 * 4 + q;
            float bb0 = __ldg(b1 + col), bb1 = __ldg(b1 + col + 1);
            buf[g * BUF_STRIDE + w] =
                h2_of(fmaxf(acc[n8][0] + bb0, 0.f), fmaxf(acc[n8][1] + bb1, 0.f));
            buf[(g + 8) * BUF_STRIDE + w] =
                h2_of(fmaxf(acc[n8][2] + bb0, 0.f), fmaxf(acc[n8][3] + bb1, 0.f));
        }
        __syncwarp();

        // ---- 6. layer2: acc3 = H @ w2^T  (K=128, N=64) + output ----
        float acc3[8][4];
        gemm16<8, 8>(buf, Wp2, g, q, lane, acc3);

#pragma unroll
        for (int n8 = 0; n8 < 8; n8++) {
            int col = n8 * 8 + 2 * q;
            float bb0 = __ldg(b2 + col), bb1 = __ldg(b2 + col + 1);
            int r0 = rowb + g;
            if (r0 < n) {
                float2 o = { acc3[n8][0] + bb0, acc3[n8][1] + bb1 };
                *(float2*)(out + (size_t)r0 * 64 + col) = o;
            }
            if (r0 + 8 < n) {
                float2 o = { acc3[n8][2] + bb0, acc3[n8][3] + bb1 };
                *(float2*)(out + (size_t)(r0 + 8) * 64 + col) = o;
            }
        }
        __syncwarp();
    }
}

extern "C" void kernel_launch(void* const* d_in, const int* in_sizes, int n_in,
                              void* d_out, int out_size) {
    const float* pts = (const float*)d_in[0];
    const float* p0  = (const float*)d_in[1];
    const float* p1  = (const float*)d_in[2];
    const float* p2  = (const float*)d_in[3];
    const float* p3  = (const float*)d_in[4];
    const float* w0  = (const float*)d_in[5];
    const float* b0  = (const float*)d_in[6];
    const float* w1  = (const float*)d_in[7];
    const float* b1  = (const float*)d_in[8];
    const float* w2  = (const float*)d_in[9];
    const float* b2  = (const float*)d_in[10];

    int n = in_sizes[0] / 4;
    int ntiles = (n + 255) / 256;

    int sm_count = 148;
    cudaDeviceGetAttribute(&sm_count, cudaDevAttrMultiProcessorCount, 0);

    cudaFuncSetAttribute(fused_kernel, cudaFuncAttributeMaxDynamicSharedMemorySize, SM_BYTES);

    prep_kernel<<<6912, 512>>>(p0, p1, p2, p3);
    fused_kernel<<<sm_count, 512, SM_BYTES>>>(
        (const float4*)pts, w0, b0, w1, b1, w2, b2, (float*)d_out, n, ntiles);
}

// round 8
// speedup vs baseline: 12.8166x; 1.1259x over previous
#include <cuda_runtime.h>
#include <cuda_fp16.h>
#include <cstdint>

#define H_RES 150

// Transposed planes: per scale s (W = 64<<s), layout [3, H, W, 16].
__device__ __align__(16) float g_planes[6912000];

// smem words: fp16 weights [0,16384); per-pair buf [32][68] at 16384 + pair*2176
#define OFF_BUF    16384
#define BUF_STRIDE 68
#define PAIR_WORDS 2176
#define SM_BYTES   135168

__device__ __forceinline__ uint32_t h2_of(float a, float b) {
    __half2 h = __float22half2_rn(make_float2(a, b));   // .x = low half
    return *(uint32_t*)&h;
}

__device__ __forceinline__ void mma16(float d[4], uint32_t a0, uint32_t a1,
                                      uint32_t a2, uint32_t a3,
                                      uint32_t b0, uint32_t b1) {
    asm volatile(
        "mma.sync.aligned.m16n8k16.row.col.f32.f16.f16.f32 "
        "{%0,%1,%2,%3}, {%4,%5,%6,%7}, {%8,%9}, {%0,%1,%2,%3};"
        : "+f"(d[0]), "+f"(d[1]), "+f"(d[2]), "+f"(d[3])
        : "r"(a0), "r"(a1), "r"(a2), "r"(a3), "r"(b0), "r"(b1));
}

// GEMM over 2 m16 tiles (rows 0-15, 16-31) and a half-N slice.
// A: [32 x 8*KC] fp16 words, stride BUF_STRIDE. Wp pre-offset by n8off*32.
// NTT = total n8 tiles in packing (k-stride); NTH = tiles this warp computes.
template<int KC, int NTT, int NTH>
__device__ __forceinline__ void gemm2m(const uint32_t* __restrict__ A,
                                       const uint2* __restrict__ Wp,
                                       int g, int q, int lane, float acc[2][NTH][4]) {
#pragma unroll
    for (int mt = 0; mt < 2; mt++)
#pragma unroll
        for (int n8 = 0; n8 < NTH; n8++)
#pragma unroll
            for (int i = 0; i < 4; i++) acc[mt][n8][i] = 0.f;

    const uint32_t* r0lo = A + g * BUF_STRIDE;
    const uint32_t* r0hi = A + (g + 8) * BUF_STRIDE;
    const uint32_t* r1lo = A + (g + 16) * BUF_STRIDE;
    const uint32_t* r1hi = A + (g + 24) * BUF_STRIDE;

#pragma unroll
    for (int k16 = 0; k16 < KC; k16++) {
        int cw = k16 * 8 + q;
        uint32_t a00 = r0lo[cw], a01 = r0hi[cw], a02 = r0lo[cw + 4], a03 = r0hi[cw + 4];
        uint32_t a10 = r1lo[cw], a11 = r1hi[cw], a12 = r1lo[cw + 4], a13 = r1hi[cw + 4];
        const uint2* W2 = Wp + (size_t)(k16 * NTT) * 32 + lane;
#pragma unroll
        for (int n8 = 0; n8 < NTH; n8++) {
            uint2 b = W2[n8 * 32];
            mma16(acc[0][n8], a00, a01, a02, a03, b.x, b.y);
            mma16(acc[1][n8], a10, a11, a12, a13, b.x, b.y);
        }
    }
}

// ---- prologue: transpose all 4 plane sets [3,16,150,W]->[3,150,W,16] ----
__global__ void prep_kernel(const float* __restrict__ p0, const float* __restrict__ p1,
                            const float* __restrict__ p2, const float* __restrict__ p3) {
    const int total = 6912000;
    for (int i = blockIdx.x * blockDim.x + threadIdx.x; i < total;
         i += gridDim.x * blockDim.x) {
        int s, base;
        const float* src;
        if (i < 460800)       { s = 0; base = 0;       src = p0; }
        else if (i < 1382400) { s = 1; base = 460800;  src = p1; }
        else if (i < 3225600) { s = 2; base = 1382400; src = p2; }
        else                  { s = 3; base = 3225600; src = p3; }
        int W = 64 << s;
        int li = i - base;
        int c = li & 15;
        int rest = li >> 4;
        int x = rest % W; rest /= W;
        int y = rest % H_RES;
        int p = rest / H_RES;
        g_planes[i] = src[((p * 16 + c) * H_RES + y) * W + x];
    }
}

// ---- persistent fused kernel: 8 warp-pairs, pair owns 32 pts, N split across pair ----
__global__ void __launch_bounds__(512, 1) fused_kernel(
    const float4* __restrict__ pts,
    const float*  __restrict__ w0, const float* __restrict__ b0,
    const float*  __restrict__ w1, const float* __restrict__ b1,
    const float*  __restrict__ w2, const float* __restrict__ b2,
    float*        __restrict__ out, int n, int ntiles)
{
    extern __shared__ uint32_t sm[];
    const int tid  = threadIdx.x;
    const int lane = tid & 31;
    const int g    = lane >> 2;
    const int q    = lane & 3;
    const int wrp  = tid >> 5;
    const int pair = wrp >> 1;
    const int half = wrp & 1;          // N-half this warp computes
    const int bar  = pair + 1;         // named barrier id 1..8

    // ---- stage fp16 weights once, fragment-packed uint2 ----
    for (int e = tid; e < 8192; e += 512) {
        const float* W; int K, nt, le;
        if (e < 2048)      { W = w0; K = 64;  nt = 16; le = e; }
        else if (e < 6144) { W = w1; K = 128; nt = 16; le = e - 2048; }
        else               { W = w2; K = 128; nt = 8;  le = e - 6144; }
        int perk = nt * 32;
        int k16 = le / perk;
        int r   = le % perk;
        int n8  = r >> 5;
        int ln  = r & 31;
        int nrow = n8 * 8 + (ln >> 2);
        int kb   = k16 * 16 + 2 * (ln & 3);
        const float* src = W + nrow * K + kb;
        uint2 v = { h2_of(src[0], src[1]), h2_of(src[8], src[9]) };
        ((uint2*)sm)[e] = v;
    }
    __syncthreads();

    uint32_t* buf = sm + OFF_BUF + pair * PAIR_WORDS;   // per-pair [32][68]
    const uint2* Wp0 = (const uint2*)sm         + half * 8 * 32;
    const uint2* Wp1 = (const uint2*)sm + 2048  + half * 8 * 32;
    const uint2* Wp2 = (const uint2*)sm + 6144  + half * 4 * 32;

    const int scale_off[4] = {0, 460800, 1382400, 3225600};

    const int ch4  = lane & 3;    // channel chunk (4 channels)
    const int pidx = lane >> 2;   // point index within pass (0..7)

#define PBAR() asm volatile("bar.sync %0, 64;" :: "r"(bar) : "memory")

    for (int t = blockIdx.x; t < ntiles; t += gridDim.x) {
        const int rowb = t * 256 + pair * 32;

        // ---- 1. sampling: warp samples its 16 rows (half*16 ..) ----
#pragma unroll
        for (int pass = 0; pass < 2; pass++) {
            const int pr = half * 16 + pass * 8 + pidx;
            int ptc = min(rowb + pr, n - 1);
            float4 P = pts[ptc];

            float fy = (P.w + 1.0f) * 0.5f * (float)(H_RES - 1);
            fy = fminf(fmaxf(fy, 0.0f), (float)(H_RES - 1));
            int   iy0 = (int)floorf(fy);
            int   iy1 = min(iy0 + 1, H_RES - 1);
            float wyv = fy - (float)iy0;
            float coord[3] = {P.x, P.y, P.z};

#pragma unroll
            for (int s = 0; s < 4; s++) {
                const int W = 64 << s;
                float prod[4] = {1.f, 1.f, 1.f, 1.f};
#pragma unroll
                for (int p = 0; p < 3; p++) {
                    float x  = coord[p];
                    float fx = (x + 1.0f) * 0.5f * (float)(W - 1);
                    fx = fminf(fmaxf(fx, 0.0f), (float)(W - 1));
                    int   ix0 = (int)floorf(fx);
                    int   ix1 = min(ix0 + 1, W - 1);
                    float wx  = fx - (float)ix0;

                    const float4* pb4 = (const float4*)(g_planes + scale_off[s]
                                                        + p * (H_RES * W * 16));
                    float4 a = pb4[(iy0 * W + ix0) * 4 + ch4];
                    float4 b = pb4[(iy0 * W + ix1) * 4 + ch4];
                    float4 c = pb4[(iy1 * W + ix0) * 4 + ch4];
                    float4 d = pb4[(iy1 * W + ix1) * 4 + ch4];

                    float w00 = (1.0f - wx) * (1.0f - wyv);
                    float w01 = wx * (1.0f - wyv);
                    float w10 = (1.0f - wx) * wyv;
                    float w11 = wx * wyv;

                    prod[0] *= a.x*w00 + b.x*w01 + c.x*w10 + d.x*w11;
                    prod[1] *= a.y*w00 + b.y*w01 + c.y*w10 + d.y*w11;
                    prod[2] *= a.z*w00 + b.z*w01 + c.z*w10 + d.z*w11;
                    prod[3] *= a.w*w00 + b.w*w01 + c.w*w10 + d.w*w11;
                }
                uint2 v = { h2_of(prod[0], prod[1]), h2_of(prod[2], prod[3]) };
                *(uint2*)(buf + pr * BUF_STRIDE + s * 8 + ch4 * 2) = v;
            }
        }
        PBAR();

        // ---- 2. layer0: acc = F[32x64] @ w0^T (half-N) ----
        float acc[2][8][4];
        gemm2m<4, 16, 8>(buf, Wp0, g, q, lane, acc);
        PBAR();

        // ---- 3. epilogue0: H(half cols) = fp16(relu(acc + b0)) ----
#pragma unroll
        for (int n8 = 0; n8 < 8; n8++) {
            int col = (half * 8 + n8) * 8 + 2 * q;
            int w   = (half * 8 + n8) * 4 + q;
            float bb0 = __ldg(b0 + col), bb1 = __ldg(b0 + col + 1);
#pragma unroll
            for (int mt = 0; mt < 2; mt++) {
                buf[(mt * 16 + g) * BUF_STRIDE + w] =
                    h2_of(fmaxf(acc[mt][n8][0] + bb0, 0.f), fmaxf(acc[mt][n8][1] + bb1, 0.f));
                buf[(mt * 16 + g + 8) * BUF_STRIDE + w] =
                    h2_of(fmaxf(acc[mt][n8][2] + bb0, 0.f), fmaxf(acc[mt][n8][3] + bb1, 0.f));
            }
        }
        PBAR();

        // ---- 4. layer1: acc = H[32x128] @ w1^T (half-N) ----
        gemm2m<8, 16, 8>(buf, Wp1, g, q, lane, acc);
        PBAR();

        // ---- 5. epilogue1: H(half cols) = fp16(relu(acc + b1)) ----
#pragma unroll
        for (int n8 = 0; n8 < 8; n8++) {
            int col = (half * 8 + n8) * 8 + 2 * q;
            int w   = (half * 8 + n8) * 4 + q;
            float bb0 = __ldg(b1 + col), bb1 = __ldg(b1 + col + 1);
#pragma unroll
            for (int mt = 0; mt < 2; mt++) {
                buf[(mt * 16 + g) * BUF_STRIDE + w] =
                    h2_of(fmaxf(acc[mt][n8][0] + bb0, 0.f), fmaxf(acc[mt][n8][1] + bb1, 0.f));
                buf[(mt * 16 + g + 8) * BUF_STRIDE + w] =
                    h2_of(fmaxf(acc[mt][n8][2] + bb0, 0.f), fmaxf(acc[mt][n8][3] + bb1, 0.f));
            }
        }
        PBAR();

        // ---- 6. layer2: acc3 = H @ w2^T (half of N=64) + output ----
        float acc3[2][4][4];
        gemm2m<8, 8, 4>(buf, Wp2, g, q, lane, acc3);

#pragma unroll
        for (int n8 = 0; n8 < 4; n8++) {
            int col = (half * 4 + n8) * 8 + 2 * q;
            float bb0 = __ldg(b2 + col), bb1 = __ldg(b2 + col + 1);
#pragma unroll
            for (int mt = 0; mt < 2; mt++) {
                int r0 = rowb + mt * 16 + g;
                if (r0 < n) {
                    float2 o = { acc3[mt][n8][0] + bb0, acc3[mt][n8][1] + bb1 };
                    *(float2*)(out + (size_t)r0 * 64 + col) = o;
                }
                if (r0 + 8 < n) {
                    float2 o = { acc3[mt][n8][2] + bb0, acc3[mt][n8][3] + bb1 };
                    *(float2*)(out + (size_t)(r0 + 8) * 64 + col) = o;
                }
            }
        }
        PBAR();   // buf (H) fully consumed before next tile's sampling overwrites
    }
#undef PBAR
}

extern "C" void kernel_launch(void* const* d_in, const int* in_sizes, int n_in,
                              void* d_out, int out_size) {
    const float* pts = (const float*)d_in[0];
    const float* p0  = (const float*)d_in[1];
    const float* p1  = (const float*)d_in[2];
    const float* p2  = (const float*)d_in[3];
    const float* p3  = (const float*)d_in[4];
    const float* w0  = (const float*)d_in[5];
    const float* b0  = (const float*)d_in[6];
    const float* w1  = (const float*)d_in[7];
    const float* b1  = (const float*)d_in[8];
    const float* w2  = (const float*)d_in[9];
    const float* b2  = (const float*)d_in[10];

    int n = in_sizes[0] / 4;
    int ntiles = (n + 255) / 256;

    int sm_count = 148;
    cudaDeviceGetAttribute(&sm_count, cudaDevAttrMultiProcessorCount, 0);

    cudaFuncSetAttribute(fused_kernel, cudaFuncAttributeMaxDynamicSharedMemorySize, SM_BYTES);

    prep_kernel<<<6912, 512>>>(p0, p1, p2, p3);
    fused_kernel<<<sm_count, 512, SM_BYTES>>>(
        (const float4*)pts, w0, b0, w1, b1, w2, b2, (float*)d_out, n, ntiles);
}